// round 6
// baseline (speedup 1.0000x reference)
#include <cuda_runtime.h>
#include <cstdint>
#include <cstddef>

#define Bz 64
#define Sz 2048
#define Hz 256

typedef unsigned long long ull;

// ---------------- scratch (static device arrays: no runtime allocation) -----
__device__ float g_A0[(size_t)Bz * Sz * Hz];   // x@w_h0 + b_h0, [B,S,H]
__device__ float g_H1[(size_t)Bz * Sz * Hz];   // h1 states,     [B,S,H]

// packed fp32x2 FMA (sm_100+)
__device__ __forceinline__ ull ffma2(ull a, ull b, ull c) {
    ull d;
    asm("fma.rn.f32x2 %0, %1, %2, %3;" : "=l"(d) : "l"(a), "l"(b), "l"(c));
    return d;
}
__device__ __forceinline__ ull dupf(float x) {
    ull r;
    asm("mov.b64 %0, {%1, %1};" : "=l"(r) : "f"(x));
    return r;
}
__device__ __forceinline__ float2 asf2(ull u) {
    float2 f;
    asm("mov.b64 {%0, %1}, %2;" : "=f"(f.x), "=f"(f.y) : "l"(u));
    return f;
}
__device__ __forceinline__ uint32_t smem_u32(const void* p) {
    return (uint32_t)__cvta_generic_to_shared(p);
}
__device__ __forceinline__ void mbar_wait_cluster(uint32_t mbar, uint32_t parity) {
    asm volatile(
        "{\n\t"
        ".reg .pred P;\n\t"
        "WLP_%=:\n\t"
        "mbarrier.try_wait.parity.acquire.cluster.shared::cta.b64 P, [%0], %1;\n\t"
        "@!P bra WLP_%=;\n\t"
        "}\n\t"
        :: "r"(mbar), "r"(parity) : "memory");
}

// ---------------- C[M,256] = A[M,256] @ W[256,256] + bias (f32x2 math) ------
__global__ __launch_bounds__(256) void gemm256(const float* __restrict__ A,
                                               const float* __restrict__ W,
                                               const float* __restrict__ bias,
                                               float* __restrict__ C) {
    __shared__ float As[64][68];
    __shared__ float Ws[64][64];
    const int tid = threadIdx.x;
    const int tm = tid >> 4, tn = tid & 15;
    const int m0 = blockIdx.x * 64, n0 = blockIdx.y * 64;

    ull acc[4][2];
#pragma unroll
    for (int i = 0; i < 4; ++i) { acc[i][0] = 0ull; acc[i][1] = 0ull; }
    const float4 bv = *(const float4*)&bias[n0 + tn * 4];

    for (int k0 = 0; k0 < 256; k0 += 64) {
#pragma unroll
        for (int f = 0; f < 4; ++f) {
            int v  = tid + f * 256;
            int r0 = v >> 4;
            int c4 = (v & 15) << 2;
            *(float4*)&As[r0][c4] = *(const float4*)&A[(size_t)(m0 + r0) * 256 + k0 + c4];
            *(float4*)&Ws[r0][c4] = *(const float4*)&W[(size_t)(k0 + r0) * 256 + n0 + c4];
        }
        __syncthreads();
#pragma unroll 8
        for (int kk = 0; kk < 64; ++kk) {
            ulonglong2 wv = *(const ulonglong2*)&Ws[kk][tn * 4];
#pragma unroll
            for (int i = 0; i < 4; ++i) {
                ull d = dupf(As[tm * 4 + i][kk]);
                acc[i][0] = ffma2(d, wv.x, acc[i][0]);
                acc[i][1] = ffma2(d, wv.y, acc[i][1]);
            }
        }
        __syncthreads();
    }
#pragma unroll
    for (int i = 0; i < 4; ++i) {
        float2 lo = asf2(acc[i][0]), hi = asf2(acc[i][1]);
        float4 o = make_float4(lo.x + bv.x, lo.y + bv.y, hi.x + bv.z, hi.y + bv.w);
        *(float4*)&C[(size_t)(m0 + tm * 4 + i) * 256 + n0 + tn * 4] = o;
    }
}

// ---------------- persistent clustered recurrence (DSMEM + mbarrier) --------
// 32 clusters x 4 CTAs x 512 threads. Cluster g owns batch rows {2g, 2g+1};
// CTA rank r owns columns [64r, 64r+64) of u_h0 / w_h1 / u_h1 (in REGISTERS).
// State exchange: producers st.shared::cluster duplicated values directly into
// every cluster CTA's double-buffered smem. Sync: one mbarrier parity
// rendezvous per step (4 release-arrives -> acquire-wait at top of next step).
// Pipeline per interval t:
//   G0: h0n[t]   = tanh(A0[t] + h0n[t-1]@u_h0)    -> DSMEM buf (t+1)&1
//   G1: a1[t-1]  = h0n[t-1]@w_h1 + b_h1           -> local smem ring
//   G2: h1n[t-2] = tanh(a1[t-2] + h1n[t-3]@u_h1)  -> DSMEM buf (t+1)&1, g_H1

#define PS 392   // partial row stride (floats), 384 used

__global__ void __cluster_dims__(4, 1, 1) __launch_bounds__(512, 1)
rnn_k(const float* __restrict__ u_h0, const float* __restrict__ w_h1,
      const float* __restrict__ u_h1, const float* __restrict__ b_h1,
      float* __restrict__ hf) {
    __shared__ float hs0[2][1024];      // [par][k*4 + 2b + {0,1}] dup h0n
    __shared__ float hs1[2][1024];      // [par][k*4 + 2b + {0,1}] dup h1n
    __shared__ float ps[16 * PS];       // k-split partials
    __shared__ float a1s[2 * 128];      // local a1 ring
    __shared__ ull   mbar;              // step rendezvous barrier

    const int tid = threadIdx.x;
    const int ks  = tid >> 5;                 // warp id = k-split (16)
    const int jg  = tid & 31;                 // lane = j-group (2 cols)
    const int bg  = (blockIdx.x >> 2) * 2;    // first batch row of cluster
    const int j0  = (blockIdx.x & 3) * 64;    // first col of this CTA

    // ---- persistent weights in registers: 3 x 16 packed col-pairs ----
    ull wr0[16], wr1[16], wr2[16];
#pragma unroll
    for (int kk = 0; kk < 16; ++kk) {
        size_t o = (size_t)(ks * 16 + kk) * 256 + j0 + jg * 2;
        wr0[kk] = __ldg((const ull*)&u_h0[o]);
        wr1[kk] = __ldg((const ull*)&w_h1[o]);
        wr2[kk] = __ldg((const ull*)&u_h1[o]);
    }

    // ---- zero state double-buffers (initial h = 0) ----
    for (int i = tid; i < 2048; i += 512) {
        ((float*)hs0)[i] = 0.f;
        ((float*)hs1)[i] = 0.f;
    }

    const uint32_t hs0_u  = smem_u32(&hs0[0][0]);
    const uint32_t d_hs1  = smem_u32(&hs1[0][0]) - hs0_u;
    const uint32_t mbar_u = smem_u32(&mbar);

    uint32_t peer[4];                         // peer hs0 base addrs
#pragma unroll
    for (int r = 0; r < 4; ++r)
        asm("mapa.shared::cluster.u32 %0, %1, %2;" : "=r"(peer[r]) : "r"(hs0_u), "r"(r));

    if (tid == 0)
        asm volatile("mbarrier.init.shared.b64 [%0], %1;" :: "r"(mbar_u), "r"(4) : "memory");
    __syncthreads();
    // full cluster sync once: mbar init + zeroed buffers visible cluster-wide
    asm volatile("barrier.cluster.arrive.aligned;" ::: "memory");
    asm volatile("barrier.cluster.wait.aligned;" ::: "memory");

    // epilogue identity: threads [0,384): o = m*128 + b*64 + j
    const int eo = tid;
    const int em = eo >> 7;
    const int er = eo & 127;
    const int eb = er >> 6;
    const int ej = er & 63;
    const float bias = b_h1[j0 + ej];

    for (int t = 0; t < Sz + 2; ++t) {
        // A0 prefetch for G0 epilogue (issued before the rendezvous wait)
        float a0v = 0.f;
        if (em == 0 && eo < 128 && t < Sz)
            a0v = __ldcg(&g_A0[((size_t)(bg + eb) * Sz + t) * 256 + j0 + ej]);

        // rendezvous: step-(t-1) DSMEM stores from all CTAs are now visible
        if (t > 0) mbar_wait_cluster(mbar_u, (t - 1) & 1);

        // ---- main: 3 GEMM partials, weights in regs, states broadcast LDS ----
        ull a00 = 0, a01 = 0, a10 = 0, a11 = 0, a20 = 0, a21 = 0;
        {
            const float* h0p = &hs0[t & 1][ks * 64];
            const float* h1p = &hs1[t & 1][ks * 64];
#pragma unroll
            for (int kk = 0; kk < 16; ++kk) {
                ulonglong2 h0 = *(const ulonglong2*)(h0p + kk * 4);
                ulonglong2 h1 = *(const ulonglong2*)(h1p + kk * 4);
                a00 = ffma2(h0.x, wr0[kk], a00);
                a01 = ffma2(h0.y, wr0[kk], a01);
                a10 = ffma2(h0.x, wr1[kk], a10);
                a11 = ffma2(h0.y, wr1[kk], a11);
                a20 = ffma2(h1.x, wr2[kk], a20);
                a21 = ffma2(h1.y, wr2[kk], a21);
            }
        }
        // store k-split partials: ps[ks][m*128 + b*64 + jg*2]
        {
            float* pb = ps + ks * PS + jg * 2;
            *(ull*)&pb[0]   = a00;  *(ull*)&pb[64]  = a01;
            *(ull*)&pb[128] = a10;  *(ull*)&pb[192] = a11;
            *(ull*)&pb[256] = a20;  *(ull*)&pb[320] = a21;
        }
        __syncthreads();

        // ---- reduce 16 partials + epilogue (DSMEM publish) ----
        if (eo < 384) {
            float s = 0.f;
#pragma unroll
            for (int p = 0; p < 16; ++p) s += ps[p * PS + eo];

            const uint32_t par1 = (t + 1) & 1;
            const uint32_t kofs = (par1 << 12) + (((j0 + ej) * 4 + 2 * eb) << 2);
            if (em == 0) {
                if (t < Sz) {
                    float v = tanhf(s + a0v);
                    ull dv = dupf(v);
#pragma unroll
                    for (int r = 0; r < 4; ++r)
                        asm volatile("st.shared::cluster.u64 [%0], %1;"
                                     :: "r"(peer[r] + kofs), "l"(dv) : "memory");
                    if (t == Sz - 1) hf[((bg + eb) * 2 + 0) * 256 + j0 + ej] = v;
                }
            } else if (em == 1) {
                if (t >= 1 && t <= Sz)
                    a1s[((t - 1) & 1) * 128 + er] = s + bias;   // a1[t-1]
            } else {
                if (t >= 2) {
                    float v = tanhf(s + a1s[(t & 1) * 128 + er]); // + a1[t-2]
                    if (t <= Sz) {                // h1n[Sz-1] never re-consumed
                        ull dv = dupf(v);
#pragma unroll
                        for (int r = 0; r < 4; ++r)
                            asm volatile("st.shared::cluster.u64 [%0], %1;"
                                         :: "r"(peer[r] + d_hs1 + kofs), "l"(dv) : "memory");
                    }
                    g_H1[((size_t)(bg + eb) * Sz + (t - 2)) * 256 + j0 + ej] = v;
                    if (t == Sz + 1) hf[((bg + eb) * 2 + 1) * 256 + j0 + ej] = v;
                }
            }
        }
        __syncthreads();                          // all DSMEM stores issued

        // release-arrive on every cluster CTA's mbarrier (threads 0..3)
        if (t < Sz + 1 && tid < 4) {
            uint32_t rm;
            asm("mapa.shared::cluster.u32 %0, %1, %2;" : "=r"(rm) : "r"(mbar_u), "r"(tid));
            asm volatile("mbarrier.arrive.release.cluster.shared::cluster.b64 _, [%0];"
                         :: "r"(rm) : "memory");
        }
    }

    // straggler guard: no CTA exits while remote stores could target it
    asm volatile("barrier.cluster.arrive.aligned;" ::: "memory");
    asm volatile("barrier.cluster.wait.aligned;" ::: "memory");
}

// ---------------- launch ----------------------------------------------------
extern "C" void kernel_launch(void* const* d_in, const int* in_sizes, int n_in,
                              void* d_out, int out_size) {
    const float* x    = (const float*)d_in[0];
    const float* w_h0 = (const float*)d_in[1];
    const float* u_h0 = (const float*)d_in[2];
    const float* b_h0 = (const float*)d_in[3];
    const float* w_h1 = (const float*)d_in[4];
    const float* u_h1 = (const float*)d_in[5];
    const float* b_h1 = (const float*)d_in[6];
    const float* w_q  = (const float*)d_in[7];
    const float* b_q  = (const float*)d_in[8];

    float* out = (float*)d_out;                       // [B,S,O]
    float* hf  = out + (size_t)Bz * Sz * Hz;          // [B,2,H]

    float *pA0 = nullptr, *pH1 = nullptr;
    cudaGetSymbolAddress((void**)&pA0, g_A0);
    cudaGetSymbolAddress((void**)&pH1, g_H1);

    gemm256<<<dim3((Bz * Sz) / 64, 4), 256>>>(x, w_h0, b_h0, pA0);
    rnn_k<<<128, 512>>>(u_h0, w_h1, u_h1, b_h1, hf);
    gemm256<<<dim3((Bz * Sz) / 64, 4), 256>>>(pH1, w_q, b_q, out);
}